// round 3
// baseline (speedup 1.0000x reference)
#include <cuda_runtime.h>
#include <cstdint>

typedef unsigned long long ull;

#define LL 256
#define BB 32
#define EE 512
#define HH 768
#define VV 10000

// ---------------- scratch (device globals; no allocations) ----------------
__device__ float g_xemb[8192 * 512];          // [l*32+b][e]
__device__ float g_xp  [2 * 256 * 32 * 768];  // [d][l][b][h] preactivations
__device__ float g_yraw[2 * 256 * 32 * 768];  // [d][l][b][c] rnn outputs
__device__ float g_scale[256];
__device__ float g_shift[256];
__device__ unsigned g_bcnt[2];                // zero-init, self-resetting
__device__ volatile unsigned g_bgen[2];       // monotonic; equality-spin is wrap-safe

// ---------------- packed fp32 helpers (sm_103a f32x2 pipe) ----------------
__device__ __forceinline__ void fma2(ull& d, ull a, ull b) {
    asm("fma.rn.f32x2 %0, %1, %2, %0;" : "+l"(d) : "l"(a), "l"(b));
}
__device__ __forceinline__ ull add2(ull a, ull b) {
    ull d; asm("add.rn.f32x2 %0, %1, %2;" : "=l"(d) : "l"(a), "l"(b)); return d;
}
__device__ __forceinline__ float pair_sum(ull u) {
    float lo, hi; asm("mov.b64 {%0,%1}, %2;" : "=f"(lo), "=f"(hi) : "l"(u));
    return lo + hi;
}

// ---------------- embedding gather ----------------
__global__ void embed_kernel(const int* __restrict__ tokens, const float* __restrict__ emb) {
    int r = blockIdx.x;                 // r = l*32 + b
    int l = r >> 5, b = r & 31;
    int tok = tokens[b * LL + l];
    ((float4*)(g_xemb + (size_t)r * EE))[threadIdx.x] =
        ((const float4*)(emb + (size_t)tok * EE))[threadIdx.x];
}

// ---------------- generic GEMM: C[M=8192, N] = A * B^T + bias ----------------
// SRC=0: A = g_xemb rows [l*32+b][K].  SRC=1: A = g_yraw split layout [d][l][b][768].
// AFFINE: fold BN (per-l scale/shift) into A load.  OUTMODE 0: g_xp [d][l][b][h]; 1: out [b][l][v].
constexpr int BM = 128, BN = 64, BK = 32, TM = 8, TN = 4, ASX = 36, BSX = 36;

template<int SRC, int AFFINE, int OUTMODE>
__global__ __launch_bounds__(256) void gemm_kernel(
    const float* __restrict__ Bm, const float* __restrict__ bias1,
    const float* __restrict__ bias2, float* __restrict__ outp, int N, int K)
{
    __shared__ float As[BM * ASX];
    __shared__ float Bs[BN * BSX];
    const int tid = threadIdx.x;
    const int tx = tid & 15, ty = tid >> 4;
    const long row0 = (long)blockIdx.y * BM;
    const int col0 = blockIdx.x * BN;
    const float* A = (SRC == 0) ? g_xemb : g_yraw;

    ull acc[TM][TN];
#pragma unroll
    for (int i = 0; i < TM; i++)
#pragma unroll
        for (int j = 0; j < TN; j++) acc[i][j] = 0ull;

    float4 pa[4], pb[2];
    auto loadTile = [&](int ko) {
#pragma unroll
        for (int i = 0; i < 4; i++) {
            int idx = tid + i * 256; int r = idx >> 3, q = (idx & 7) * 4;
            long row = row0 + r;
            if (SRC == 0) {
                pa[i] = *(const float4*)(A + row * (long)K + ko + q);
            } else {
                int l = (int)(row >> 5), b = (int)(row & 31);
                int d = (ko >= 768) ? 1 : 0;
                const float* p = A + (size_t)d * 6291456u + (size_t)l * 24576u +
                                 (size_t)b * 768u + (ko - d * 768) + q;
                float4 v = *(const float4*)p;
                if (AFFINE) {
                    float sc = g_scale[l], sh = g_shift[l];
                    v.x = fmaf(v.x, sc, sh); v.y = fmaf(v.y, sc, sh);
                    v.z = fmaf(v.z, sc, sh); v.w = fmaf(v.w, sc, sh);
                }
                pa[i] = v;
            }
        }
#pragma unroll
        for (int i = 0; i < 2; i++) {
            int idx = tid + i * 256; int r = idx >> 3, q = (idx & 7) * 4;
            int gc = col0 + r;
            pb[i] = (gc < N) ? *(const float4*)(Bm + (long)gc * K + ko + q)
                             : make_float4(0.f, 0.f, 0.f, 0.f);
        }
    };

    loadTile(0);
    const int ktiles = K / BK;
    for (int kt = 0; kt < ktiles; ++kt) {
#pragma unroll
        for (int i = 0; i < 4; i++) {
            int idx = tid + i * 256; int r = idx >> 3, q = (idx & 7) * 4;
            *(float4*)(As + r * ASX + q) = pa[i];
        }
#pragma unroll
        for (int i = 0; i < 2; i++) {
            int idx = tid + i * 256; int r = idx >> 3, q = (idx & 7) * 4;
            *(float4*)(Bs + r * BSX + q) = pb[i];
        }
        __syncthreads();
        if (kt + 1 < ktiles) loadTile((kt + 1) * BK);
#pragma unroll
        for (int kp = 0; kp < 16; ++kp) {
            ull av[TM], bv[TN];
#pragma unroll
            for (int i = 0; i < TM; i++)
                av[i] = *(const ull*)(As + (ty * TM + i) * ASX + 2 * kp);
#pragma unroll
            for (int j = 0; j < TN; j++)
                bv[j] = *(const ull*)(Bs + (tx * TN + j) * BSX + 2 * kp);
#pragma unroll
            for (int i = 0; i < TM; i++)
#pragma unroll
                for (int j = 0; j < TN; j++) fma2(acc[i][j], av[i], bv[j]);
        }
        __syncthreads();
    }

#pragma unroll
    for (int i = 0; i < TM; i++) {
        long r = row0 + ty * TM + i;
        int l = (int)(r >> 5), b = (int)(r & 31);
        int n0 = col0 + tx * TN;
        if (n0 < N) {
            float4 v;
            v.x = pair_sum(acc[i][0]) + bias1[n0 + 0];
            v.y = pair_sum(acc[i][1]) + bias1[n0 + 1];
            v.z = pair_sum(acc[i][2]) + bias1[n0 + 2];
            v.w = pair_sum(acc[i][3]) + bias1[n0 + 3];
            if (bias2) {
                v.x += bias2[n0 + 0]; v.y += bias2[n0 + 1];
                v.z += bias2[n0 + 2]; v.w += bias2[n0 + 3];
            }
            if (OUTMODE == 0) {
                int d = n0 / 768, h = n0 - d * 768;
                *(float4*)(g_xp + (size_t)d * 6291456u + (size_t)l * 24576u +
                           (size_t)b * 768u + h) = v;
            } else {
                *(float4*)(outp + (size_t)b * 2560000u + (size_t)l * 10000u + n0) = v;
            }
        }
    }
}

// ---------------- persistent bidirectional RNN recurrence ----------------
// 48 CTAs: dir = blk/24, 32 columns each. W_hh slice in registers (48 packed ull
// per thread: column c0+lane, k-slice wid*96..+95). h_prev staged to smem; all
// compute a-loads are warp-uniform broadcasts. Per-direction grid barrier each step.
#define RNN_SMEM ((32 * 772 + 8 * 32 * 32) * 4)

__global__ __launch_bounds__(256) void rnn_kernel(const float* __restrict__ whh)
{
    extern __shared__ float sm[];
    float* hs = sm;                    // [32 b][772]  (h_prev, padded rows)
    float* part = sm + 32 * 772;       // [8 wid][32 b][32 c] partials
    const int tid = threadIdx.x;
    const int lane = tid & 31, wid = tid >> 5;
    const int dir = blockIdx.x / 24;
    const int c0 = (blockIdx.x % 24) * 32;

    ull Wr[48];
    {
        const float* wp = whh + (size_t)dir * 589824u + (size_t)(c0 + lane) * 768u + wid * 96;
#pragma unroll
        for (int i = 0; i < 48; i++) Wr[i] = *(const ull*)(wp + 2 * i);
    }

    const float* xpd = g_xp + (size_t)dir * 6291456u;
    float* yd = g_yraw + (size_t)dir * 6291456u;
    const int ob = tid >> 3;           // output batch row
    const int oc = (tid & 7) * 4;      // output col offset within tile

    for (int t = 0; t < LL; ++t) {
        const int l = dir ? (LL - 1 - t) : t;
        float4 xv = *(const float4*)(xpd + (size_t)l * 24576u + (size_t)ob * 768u + c0 + oc);
        float4 hv;
        if (t == 0) {
            hv.x = tanhf(xv.x); hv.y = tanhf(xv.y);
            hv.z = tanhf(xv.z); hv.w = tanhf(xv.w);
        } else {
            const int lp = dir ? (l + 1) : (l - 1);
            const float4* s4 = (const float4*)(yd + (size_t)lp * 24576u);
#pragma unroll
            for (int r2 = 0; r2 < 4; ++r2) {
                int b = wid * 4 + r2;
#pragma unroll
                for (int j = 0; j < 6; ++j) {
                    int q = lane + j * 32;
                    *(float4*)(hs + b * 772 + q * 4) = s4[b * 192 + q];
                }
            }
            __syncthreads();
#pragma unroll 1
            for (int b = 0; b < 32; ++b) {
                const ull* arow = (const ull*)(hs + b * 772 + wid * 96);
                ull a0 = 0, a1 = 0, a2 = 0, a3 = 0;
#pragma unroll
                for (int kp = 0; kp < 48; kp += 4) {
                    fma2(a0, arow[kp + 0], Wr[kp + 0]);
                    fma2(a1, arow[kp + 1], Wr[kp + 1]);
                    fma2(a2, arow[kp + 2], Wr[kp + 2]);
                    fma2(a3, arow[kp + 3], Wr[kp + 3]);
                }
                part[wid * 1024 + b * 32 + lane] = pair_sum(add2(add2(a0, a1), add2(a2, a3)));
            }
            __syncthreads();
            float s0 = xv.x, s1 = xv.y, s2 = xv.z, s3 = xv.w;
#pragma unroll
            for (int w = 0; w < 8; ++w) {
                float4 p = *(const float4*)(part + w * 1024 + ob * 32 + oc);
                s0 += p.x; s1 += p.y; s2 += p.z; s3 += p.w;
            }
            hv.x = tanhf(s0); hv.y = tanhf(s1);
            hv.z = tanhf(s2); hv.w = tanhf(s3);
        }
        *(float4*)(yd + (size_t)l * 24576u + (size_t)ob * 768u + c0 + oc) = hv;

        // per-direction grid barrier (24 CTAs)
        __threadfence();
        __syncthreads();
        if (tid == 0) {
            unsigned g = g_bgen[dir];
            if (atomicAdd(&g_bcnt[dir], 1u) == 23u) {
                g_bcnt[dir] = 0;
                __threadfence();
                g_bgen[dir] = g + 1u;
            } else {
                while (g_bgen[dir] == g) { __nanosleep(64); }
            }
        }
        __syncthreads();
    }
}

// ---------------- BN stats per timestep l over (d, b, c) ----------------
__global__ void bn_stats_kernel(const float* __restrict__ gamma, const float* __restrict__ beta)
{
    const int l = blockIdx.x, tid = threadIdx.x;
    float s = 0.f, s2 = 0.f;
#pragma unroll
    for (int d = 0; d < 2; ++d) {
        const float4* p = (const float4*)(g_yraw + (size_t)d * 6291456u + (size_t)l * 24576u);
        for (int i = tid; i < 6144; i += 256) {
            float4 v = p[i];
            s  += v.x + v.y + v.z + v.w;
            s2 += v.x * v.x + v.y * v.y + v.z * v.z + v.w * v.w;
        }
    }
    __shared__ float ss[256], st[256];
    ss[tid] = s; st[tid] = s2;
    __syncthreads();
    for (int o = 128; o > 0; o >>= 1) {
        if (tid < o) { ss[tid] += ss[tid + o]; st[tid] += st[tid + o]; }
        __syncthreads();
    }
    if (tid == 0) {
        const float inv = 1.f / 49152.f;
        float mean = ss[0] * inv;
        float var  = st[0] * inv - mean * mean;
        float sc = gamma[l] * rsqrtf(var + 1e-5f);
        g_scale[l] = sc;
        g_shift[l] = beta[l] - mean * sc;
    }
}

// ---------------- launch ----------------
extern "C" void kernel_launch(void* const* d_in, const int* in_sizes, int n_in,
                              void* d_out, int out_size) {
    (void)in_sizes; (void)n_in; (void)out_size;
    const int*   tokens   = (const int*)d_in[0];
    const float* emb      = (const float*)d_in[1];
    const float* w_ih_l0  = (const float*)d_in[2];
    const float* w_hh_l0  = (const float*)d_in[3];
    const float* b_ih_l0  = (const float*)d_in[4];
    const float* b_hh_l0  = (const float*)d_in[5];
    const float* w_ih_l1  = (const float*)d_in[6];
    const float* w_hh_l1  = (const float*)d_in[7];
    const float* b_ih_l1  = (const float*)d_in[8];
    const float* b_hh_l1  = (const float*)d_in[9];
    const float* gamma    = (const float*)d_in[10];
    const float* beta     = (const float*)d_in[11];
    const float* lin_w    = (const float*)d_in[12];
    const float* lin_b    = (const float*)d_in[13];
    float* out = (float*)d_out;

    cudaFuncSetAttribute(rnn_kernel, cudaFuncAttributeMaxDynamicSharedMemorySize, RNN_SMEM);

    embed_kernel<<<8192, 128>>>(tokens, emb);
    gemm_kernel<0, 0, 0><<<dim3(24, 64), 256>>>(w_ih_l0, b_ih_l0, b_hh_l0, nullptr, 1536, 512);
    rnn_kernel<<<48, 256, RNN_SMEM>>>(w_hh_l0);
    gemm_kernel<1, 0, 0><<<dim3(24, 64), 256>>>(w_ih_l1, b_ih_l1, b_hh_l1, nullptr, 1536, 1536);
    rnn_kernel<<<48, 256, RNN_SMEM>>>(w_hh_l1);
    bn_stats_kernel<<<256, 256>>>(gamma, beta);
    gemm_kernel<1, 1, 1><<<dim3(157, 64), 256>>>(lin_w, lin_b, nullptr, out, 10000, 1536);
}

// round 5
// speedup vs baseline: 2.2556x; 2.2556x over previous
#include <cuda_runtime.h>
#include <cuda_bf16.h>
#include <cstdint>

typedef unsigned long long ull;

#define LL 256
#define BB 32
#define EE 512
#define HH 768
#define VV 10000
#define VPAD 10112

// ---------------- scratch (device globals; no allocations) ----------------
__device__ float g_xp  [2 * 256 * 32 * 768];  // [d][l][b][h] preactivations
__device__ float g_yraw[2 * 256 * 32 * 768];  // [d][l][b][c] rnn outputs
__device__ float g_scale[256];
__device__ float g_shift[256];
__device__ unsigned g_bcnt[2];                // zero-init, self-resetting
__device__ volatile unsigned g_bgen[2];       // monotonic; equality-spin is wrap-safe

__device__ __nv_bfloat16 g_Ahi[8192 * 1536];
__device__ __nv_bfloat16 g_Alo[8192 * 1536];
__device__ __nv_bfloat16 g_Whi[VPAD * 1536];
__device__ __nv_bfloat16 g_Wlo[VPAD * 1536];

// ---------------- packed fp32 helpers (sm_103a f32x2 pipe) ----------------
__device__ __forceinline__ void fma2(ull& d, ull a, ull b) {
    asm("fma.rn.f32x2 %0, %1, %2, %0;" : "+l"(d) : "l"(a), "l"(b));
}
__device__ __forceinline__ ull add2(ull a, ull b) {
    ull d; asm("add.rn.f32x2 %0, %1, %2;" : "=l"(d) : "l"(a), "l"(b)); return d;
}
__device__ __forceinline__ float pair_sum(ull u) {
    float lo, hi; asm("mov.b64 {%0,%1}, %2;" : "=f"(lo), "=f"(hi) : "l"(u));
    return lo + hi;
}

// ---------------- warp-MMA helpers (portable PTX: sm_80+, no 'a' features) ----
__device__ __forceinline__ uint32_t smem_u32(const void* p) {
    uint32_t a;
    asm("{ .reg .u64 t; cvta.to.shared.u64 t, %1; cvt.u32.u64 %0, t; }" : "=r"(a) : "l"(p));
    return a;
}
__device__ __forceinline__ void cp16(uint32_t s, const void* g) {
    asm volatile("cp.async.cg.shared.global [%0], [%1], 16;" :: "r"(s), "l"(g));
}
#define CP_COMMIT() asm volatile("cp.async.commit_group;" ::: "memory")
#define CP_WAIT1()  asm volatile("cp.async.wait_group 1;" ::: "memory")
#define CP_WAIT0()  asm volatile("cp.async.wait_group 0;" ::: "memory")

__device__ __forceinline__ void ldsm4(uint32_t& r0, uint32_t& r1, uint32_t& r2, uint32_t& r3,
                                      uint32_t a) {
    asm volatile("ldmatrix.sync.aligned.m8n8.x4.shared.b16 {%0,%1,%2,%3}, [%4];"
                 : "=r"(r0), "=r"(r1), "=r"(r2), "=r"(r3) : "r"(a));
}
__device__ __forceinline__ void mma16816(float* c, const uint32_t* a, const uint32_t* b) {
    asm volatile("mma.sync.aligned.m16n8k16.row.col.f32.bf16.bf16.f32 "
                 "{%0,%1,%2,%3}, {%4,%5,%6,%7}, {%8,%9}, {%0,%1,%2,%3};"
                 : "+f"(c[0]), "+f"(c[1]), "+f"(c[2]), "+f"(c[3])
                 : "r"(a[0]), "r"(a[1]), "r"(a[2]), "r"(a[3]), "r"(b[0]), "r"(b[1]));
}

// ---------------- hi/lo bf16 split helpers ----------------
__device__ __forceinline__ void split4(float4 v, __nv_bfloat16* hi, __nv_bfloat16* lo) {
    __nv_bfloat16 h[4], l[4];
    float f[4] = {v.x, v.y, v.z, v.w};
#pragma unroll
    for (int i = 0; i < 4; i++) {
        h[i] = __float2bfloat16(f[i]);
        l[i] = __float2bfloat16(f[i] - __bfloat162float(h[i]));
    }
    *(uint2*)hi = *(const uint2*)h;
    *(uint2*)lo = *(const uint2*)l;
}

// ---------------- conversion kernels ----------------
__global__ void conv_emb(const int* __restrict__ tokens, const float* __restrict__ emb) {
    int r = blockIdx.x;                 // r = l*32 + b
    int l = r >> 5, b = r & 31;
    int tok = tokens[b * LL + l];
    int i = threadIdx.x;                // 128 threads x 4 floats
    float4 v = ((const float4*)(emb + (size_t)tok * EE))[i];
    split4(v, g_Ahi + (size_t)r * EE + i * 4, g_Alo + (size_t)r * EE + i * 4);
}

__global__ void conv_w(const float* __restrict__ W, int Nrows, int K) {
    int r = blockIdx.x;
    __nv_bfloat16* hi = g_Whi + (size_t)r * K;
    __nv_bfloat16* lo = g_Wlo + (size_t)r * K;
    if (r >= Nrows) {
        for (int c = threadIdx.x * 4; c < K; c += 512) {
            *(uint2*)(hi + c) = make_uint2(0, 0);
            *(uint2*)(lo + c) = make_uint2(0, 0);
        }
        return;
    }
    for (int c = threadIdx.x * 4; c < K; c += 512) {
        float4 v = *(const float4*)(W + (size_t)r * K + c);
        split4(v, hi + c, lo + c);
    }
}

template<int AFF>
__global__ void conv_y() {
    int r = blockIdx.x;
    int l = r >> 5, b = r & 31;
    float sc = AFF ? g_scale[l] : 1.f;
    float sh = AFF ? g_shift[l] : 0.f;
    for (int c0 = threadIdx.x * 4; c0 < 1536; c0 += 1024) {
        int d = (c0 >= 768) ? 1 : 0;
        int h = c0 - d * 768;
        float4 v = *(const float4*)(g_yraw + (size_t)d * 6291456u +
                                    (size_t)l * 24576u + (size_t)b * 768u + h);
        if (AFF) {
            v.x = fmaf(v.x, sc, sh); v.y = fmaf(v.y, sc, sh);
            v.z = fmaf(v.z, sc, sh); v.w = fmaf(v.w, sc, sh);
        }
        split4(v, g_Ahi + (size_t)r * 1536 + c0, g_Alo + (size_t)r * 1536 + c0);
    }
}

// ---------------- HMMA GEMM: C[8192, Ntot] = A * W^T (bf16 hi/lo, 3 chains) ----
// 128x128 CTA tile, BK=32, 8 warps (4m x 2n), warp tile 32x64 via m16n8k16.
// Smem rows at 80B stride (stride-5 in 16B units -> conflict-free ldmatrix).
// Double-buffered cp.async. Grid: x = row tile (fast) so A stays L2-resident.
#define STG 40960
#define OAH 0
#define OAL 10240
#define OBH 20480
#define OBL 30720
#define MMA_SMEM (2 * STG)

template<int EPI>   // 0: write g_xp (+bias1+bias2), 1: write logits [b][l][v] (+bias1)
__global__ __launch_bounds__(256) void mma_gemm(
    const float* __restrict__ bias1, const float* __restrict__ bias2,
    float* __restrict__ outp, int K, int Ntot)
{
    extern __shared__ char smem[];
    const uint32_t sb = smem_u32(smem);
    const int tid = threadIdx.x, wid = tid >> 5, lane = tid & 31;
    const long row0 = (long)blockIdx.x * 128;
    const long col0 = (long)blockIdx.y * 128;
    const int mbase = (wid & 3) * 32;
    const int nbase = (wid >> 2) * 64;

    // ldmatrix lane address components
    const int a_row = (lane & 7) + ((lane >> 3) & 1) * 8;  // A: matrices 0/1 rows, 2/3 k+8
    const int a_kc  = (lane >> 4);
    const int b_row = (lane & 7) + (lane >> 4) * 8;        // B: matrices 0/1 = n0-7, 2/3 = n8-15
    const int b_kc  = ((lane >> 3) & 1);

    float acc[2][8][4];
#pragma unroll
    for (int i = 0; i < 2; i++)
#pragma unroll
        for (int j = 0; j < 8; j++)
#pragma unroll
            for (int q = 0; q < 4; q++) acc[i][j][q] = 0.f;

    auto gload = [&](int ko, int st) {
        uint32_t s0 = sb + st * STG;
#pragma unroll
        for (int it = 0; it < 2; it++) {
            int idx = tid + it * 256;
            int r = idx >> 2, ch = idx & 3;
            uint32_t soff = r * 80 + ch * 16;
            long ga = (row0 + r) * (long)K + ko + ch * 8;
            long gb = (col0 + r) * (long)K + ko + ch * 8;
            cp16(s0 + OAH + soff, g_Ahi + ga);
            cp16(s0 + OAL + soff, g_Alo + ga);
            cp16(s0 + OBH + soff, g_Whi + gb);
            cp16(s0 + OBL + soff, g_Wlo + gb);
        }
    };

    const int nk = K / 32;
    gload(0, 0);
    CP_COMMIT();

    for (int it = 0; it < nk; ++it) {
        const int cur = it & 1;
        if (it + 1 < nk) {
            gload((it + 1) * 32, cur ^ 1);
            CP_COMMIT();
            CP_WAIT1();
        } else {
            CP_WAIT0();
        }
        __syncthreads();

        const uint32_t s0 = sb + cur * STG;
#pragma unroll
        for (int ks = 0; ks < 2; ++ks) {
            const int kc = ks * 2;   // 16B chunk index of this k16
            uint32_t Ah[2][4], Al[2][4], Bh[8][2], Bl[8][2];
#pragma unroll
            for (int mt = 0; mt < 2; mt++) {
                uint32_t ad = (mbase + mt * 16 + a_row) * 80 + (kc + a_kc) * 16;
                ldsm4(Ah[mt][0], Ah[mt][1], Ah[mt][2], Ah[mt][3], s0 + OAH + ad);
                ldsm4(Al[mt][0], Al[mt][1], Al[mt][2], Al[mt][3], s0 + OAL + ad);
            }
#pragma unroll
            for (int bt = 0; bt < 4; bt++) {
                uint32_t bd = (nbase + bt * 16 + b_row) * 80 + (kc + b_kc) * 16;
                ldsm4(Bh[bt * 2][0], Bh[bt * 2][1], Bh[bt * 2 + 1][0], Bh[bt * 2 + 1][1],
                      s0 + OBH + bd);
                ldsm4(Bl[bt * 2][0], Bl[bt * 2][1], Bl[bt * 2 + 1][0], Bl[bt * 2 + 1][1],
                      s0 + OBL + bd);
            }
#pragma unroll
            for (int mt = 0; mt < 2; mt++)
#pragma unroll
                for (int nt = 0; nt < 8; nt++) {
                    mma16816(acc[mt][nt], Ah[mt], Bh[nt]);
                    mma16816(acc[mt][nt], Ah[mt], Bl[nt]);
                    mma16816(acc[mt][nt], Al[mt], Bh[nt]);
                }
        }
        __syncthreads();
    }

    // epilogue
#pragma unroll
    for (int mt = 0; mt < 2; mt++) {
        int r0 = (int)row0 + mbase + mt * 16 + (lane >> 2);
        int r1 = r0 + 8;
#pragma unroll
        for (int nt = 0; nt < 8; nt++) {
            int n = (int)col0 + nbase + nt * 8 + (lane & 3) * 2;
            if (n < Ntot) {
                float2 bv = *(const float2*)(bias1 + n);
                float v00 = acc[mt][nt][0] + bv.x, v01 = acc[mt][nt][1] + bv.y;
                float v10 = acc[mt][nt][2] + bv.x, v11 = acc[mt][nt][3] + bv.y;
                if (EPI == 0) {
                    float2 b2 = *(const float2*)(bias2 + n);
                    v00 += b2.x; v01 += b2.y; v10 += b2.x; v11 += b2.y;
                    int d = (n >= 768) ? 1 : 0;
                    int h = n - d * 768;
                    float* base = g_xp + (size_t)d * 6291456u + (size_t)h;
                    int l0 = r0 >> 5, b0 = r0 & 31;
                    int l1 = r1 >> 5, b1 = r1 & 31;
                    *(float2*)(base + (size_t)l0 * 24576u + (size_t)b0 * 768u) =
                        make_float2(v00, v01);
                    *(float2*)(base + (size_t)l1 * 24576u + (size_t)b1 * 768u) =
                        make_float2(v10, v11);
                } else {
                    int l0 = r0 >> 5, b0 = r0 & 31;
                    int l1 = r1 >> 5, b1 = r1 & 31;
                    *(float2*)(outp + (size_t)b0 * 2560000u + (size_t)l0 * 10000u + n) =
                        make_float2(v00, v01);
                    *(float2*)(outp + (size_t)b1 * 2560000u + (size_t)l1 * 10000u + n) =
                        make_float2(v10, v11);
                }
            }
        }
    }
}

// ---------------- persistent bidirectional RNN recurrence (unchanged, passing) ----------------
#define RNN_SMEM ((32 * 772 + 8 * 32 * 32) * 4)

__global__ __launch_bounds__(256) void rnn_kernel(const float* __restrict__ whh)
{
    extern __shared__ float sm[];
    float* hs = sm;                    // [32 b][772]
    float* part = sm + 32 * 772;       // [8 wid][32 b][32 c]
    const int tid = threadIdx.x;
    const int lane = tid & 31, wid = tid >> 5;
    const int dir = blockIdx.x / 24;
    const int c0 = (blockIdx.x % 24) * 32;

    ull Wr[48];
    {
        const float* wp = whh + (size_t)dir * 589824u + (size_t)(c0 + lane) * 768u + wid * 96;
#pragma unroll
        for (int i = 0; i < 48; i++) Wr[i] = *(const ull*)(wp + 2 * i);
    }

    const float* xpd = g_xp + (size_t)dir * 6291456u;
    float* yd = g_yraw + (size_t)dir * 6291456u;
    const int ob = tid >> 3;
    const int oc = (tid & 7) * 4;

    for (int t = 0; t < LL; ++t) {
        const int l = dir ? (LL - 1 - t) : t;
        float4 xv = *(const float4*)(xpd + (size_t)l * 24576u + (size_t)ob * 768u + c0 + oc);
        float4 hv;
        if (t == 0) {
            hv.x = tanhf(xv.x); hv.y = tanhf(xv.y);
            hv.z = tanhf(xv.z); hv.w = tanhf(xv.w);
        } else {
            const int lp = dir ? (l + 1) : (l - 1);
            const float4* s4 = (const float4*)(yd + (size_t)lp * 24576u);
#pragma unroll
            for (int r2 = 0; r2 < 4; ++r2) {
                int b = wid * 4 + r2;
#pragma unroll
                for (int j = 0; j < 6; ++j) {
                    int q = lane + j * 32;
                    *(float4*)(hs + b * 772 + q * 4) = s4[b * 192 + q];
                }
            }
            __syncthreads();
#pragma unroll 1
            for (int b = 0; b < 32; ++b) {
                const ull* arow = (const ull*)(hs + b * 772 + wid * 96);
                ull a0 = 0, a1 = 0, a2 = 0, a3 = 0;
#pragma unroll
                for (int kp = 0; kp < 48; kp += 4) {
                    fma2(a0, arow[kp + 0], Wr[kp + 0]);
                    fma2(a1, arow[kp + 1], Wr[kp + 1]);
                    fma2(a2, arow[kp + 2], Wr[kp + 2]);
                    fma2(a3, arow[kp + 3], Wr[kp + 3]);
                }
                part[wid * 1024 + b * 32 + lane] = pair_sum(add2(add2(a0, a1), add2(a2, a3)));
            }
            __syncthreads();
            float s0 = xv.x, s1 = xv.y, s2 = xv.z, s3 = xv.w;
#pragma unroll
            for (int w = 0; w < 8; ++w) {
                float4 p = *(const float4*)(part + w * 1024 + ob * 32 + oc);
                s0 += p.x; s1 += p.y; s2 += p.z; s3 += p.w;
            }
            hv.x = tanhf(s0); hv.y = tanhf(s1);
            hv.z = tanhf(s2); hv.w = tanhf(s3);
        }
        *(float4*)(yd + (size_t)l * 24576u + (size_t)ob * 768u + c0 + oc) = hv;

        __threadfence();
        __syncthreads();
        if (tid == 0) {
            unsigned g = g_bgen[dir];
            if (atomicAdd(&g_bcnt[dir], 1u) == 23u) {
                g_bcnt[dir] = 0;
                __threadfence();
                g_bgen[dir] = g + 1u;
            } else {
                while (g_bgen[dir] == g) { __nanosleep(64); }
            }
        }
        __syncthreads();
    }
}

// ---------------- BN stats per timestep l over (d, b, c) ----------------
__global__ void bn_stats_kernel(const float* __restrict__ gamma, const float* __restrict__ beta)
{
    const int l = blockIdx.x, tid = threadIdx.x;
    float s = 0.f, s2 = 0.f;
#pragma unroll
    for (int d = 0; d < 2; ++d) {
        const float4* p = (const float4*)(g_yraw + (size_t)d * 6291456u + (size_t)l * 24576u);
        for (int i = tid; i < 6144; i += 256) {
            float4 v = p[i];
            s  += v.x + v.y + v.z + v.w;
            s2 += v.x * v.x + v.y * v.y + v.z * v.z + v.w * v.w;
        }
    }
    __shared__ float ss[256], st[256];
    ss[tid] = s; st[tid] = s2;
    __syncthreads();
    for (int o = 128; o > 0; o >>= 1) {
        if (tid < o) { ss[tid] += ss[tid + o]; st[tid] += st[tid + o]; }
        __syncthreads();
    }
    if (tid == 0) {
        const float inv = 1.f / 49152.f;
        float mean = ss[0] * inv;
        float var  = st[0] * inv - mean * mean;
        float sc = gamma[l] * rsqrtf(var + 1e-5f);
        g_scale[l] = sc;
        g_shift[l] = beta[l] - mean * sc;
    }
}

// ---------------- launch ----------------
extern "C" void kernel_launch(void* const* d_in, const int* in_sizes, int n_in,
                              void* d_out, int out_size) {
    (void)in_sizes; (void)n_in; (void)out_size;
    const int*   tokens   = (const int*)d_in[0];
    const float* emb      = (const float*)d_in[1];
    const float* w_ih_l0  = (const float*)d_in[2];
    const float* w_hh_l0  = (const float*)d_in[3];
    const float* b_ih_l0  = (const float*)d_in[4];
    const float* b_hh_l0  = (const float*)d_in[5];
    const float* w_ih_l1  = (const float*)d_in[6];
    const float* w_hh_l1  = (const float*)d_in[7];
    const float* b_ih_l1  = (const float*)d_in[8];
    const float* b_hh_l1  = (const float*)d_in[9];
    const float* gamma    = (const float*)d_in[10];
    const float* beta     = (const float*)d_in[11];
    const float* lin_w    = (const float*)d_in[12];
    const float* lin_b    = (const float*)d_in[13];
    float* out = (float*)d_out;

    cudaFuncSetAttribute(rnn_kernel, cudaFuncAttributeMaxDynamicSharedMemorySize, RNN_SMEM);
    cudaFuncSetAttribute(mma_gemm<0>, cudaFuncAttributeMaxDynamicSharedMemorySize, MMA_SMEM);
    cudaFuncSetAttribute(mma_gemm<1>, cudaFuncAttributeMaxDynamicSharedMemorySize, MMA_SMEM);

    // layer 0 input GEMM (K=512)
    conv_emb<<<8192, 128>>>(tokens, emb);
    conv_w<<<1536, 128>>>(w_ih_l0, 1536, 512);
    mma_gemm<0><<<dim3(64, 12), 256, MMA_SMEM>>>(b_ih_l0, b_hh_l0, nullptr, 512, 1536);
    rnn_kernel<<<48, 256, RNN_SMEM>>>(w_hh_l0);

    // layer 1 input GEMM (K=1536)
    conv_y<0><<<8192, 256>>>();
    conv_w<<<1536, 128>>>(w_ih_l1, 1536, 1536);
    mma_gemm<0><<<dim3(64, 12), 256, MMA_SMEM>>>(b_ih_l1, b_hh_l1, nullptr, 1536, 1536);
    rnn_kernel<<<48, 256, RNN_SMEM>>>(w_hh_l1);

    // BN + final projection (K=1536, N=10000)
    bn_stats_kernel<<<256, 256>>>(gamma, beta);
    conv_y<1><<<8192, 256>>>();
    conv_w<<<VPAD, 128>>>(lin_w, VV, 1536);
    mma_gemm<1><<<dim3(64, 79), 256, MMA_SMEM>>>(lin_b, nullptr, out, 1536, VV);
}